// round 4
// baseline (speedup 1.0000x reference)
#include <cuda_runtime.h>
#include <cuda_bf16.h>
#include <math.h>
#include <stdint.h>

#define S 128
#define B 32
#define H 1024
#define E 1024
#define V 32000
#define SB (S*B)        /* 4096  */
#define BH (B*H)        /* 32768 */

// ---------------- scratch (device globals; no allocations allowed) ----------
__device__ float g_embeds[SB*H];   // embeds for layer1, reused as l2_out
__device__ float g_xi[SB*H];
__device__ float g_xf[SB*H];
__device__ float g_l1[SB*H];
__device__ float g_latA[BH];
__device__ float g_latB[BH];
__device__ float g_part[2*8*B*H];  // [gate][kc8][b][h]
__device__ unsigned g_cnt[2*S*16]; // per (layer,t,htile) arrival counters
__device__ float g_WhiT[H*H];
__device__ float g_WhfT[H*H];
__device__ float g_Whi2T[H*H];
__device__ float g_Whf2T[H*H];
// bf16 split operands for tensor-core GEMMs
__device__ __nv_bfloat16 g_Ah[SB*H];
__device__ __nv_bfloat16 g_Al[SB*H];
__device__ __nv_bfloat16 g_Bh[(size_t)V*H];
__device__ __nv_bfloat16 g_Bl[(size_t)V*H];

// ============================ helpers ========================================
__device__ __forceinline__ uint32_t smem_u32(const void* p) {
    uint32_t a;
    asm("{ .reg .u64 t; cvta.to.shared.u64 t, %1; cvt.u32.u64 %0, t; }"
        : "=r"(a) : "l"(p));
    return a;
}
__device__ __forceinline__ void cpa16(uint32_t s, const void* g) {
    asm volatile("cp.async.cg.shared.global [%0], [%1], 16;" :: "r"(s), "l"(g) : "memory");
}
#define LDSM_X4(r0,r1,r2,r3,addr) \
    asm volatile("ldmatrix.sync.aligned.m8n8.x4.shared.b16 {%0,%1,%2,%3}, [%4];" \
        : "=r"(r0),"=r"(r1),"=r"(r2),"=r"(r3) : "r"(addr))
#define MMA_BF16(c, a, b0, b1) \
    asm volatile("mma.sync.aligned.m16n8k16.row.col.f32.bf16.bf16.f32 " \
        "{%0,%1,%2,%3}, {%4,%5,%6,%7}, {%8,%9}, {%0,%1,%2,%3};" \
        : "+f"((c)[0]),"+f"((c)[1]),"+f"((c)[2]),"+f"((c)[3]) \
        : "r"((a)[0]),"r"((a)[1]),"r"((a)[2]),"r"((a)[3]), "r"(b0),"r"(b1))

// ================= split-bf16 HMMA GEMM ======================================
// C[M,Nld](fp32) = Ah*Bh^T + Al*Bh^T + Ah*Bl^T + bias
// block tile 128x128, BK=32, 3-stage cp.async pipeline, 256 threads
// (warps 2M x 4N, warp tile 64x32). smem rows 80B pitch -> conflict-free ldsm.
#define ROWP 40                      /* bf16 elems per smem row (80B) */
#define MAT_B (128*ROWP*2)           /* 10240 bytes per matrix tile   */
#define STG_B (4*MAT_B)              /* 40960 bytes per stage         */
#define GEMM_SMEM (3*STG_B)          /* 122880                        */

__global__ void __launch_bounds__(256, 1)
k_hmma(const __nv_bfloat16* __restrict__ Ah, const __nv_bfloat16* __restrict__ Al,
       const __nv_bfloat16* __restrict__ Bh, const __nv_bfloat16* __restrict__ Bl,
       const float* __restrict__ bias, float* __restrict__ C,
       int Kdim, int Nld)
{
    extern __shared__ __align__(16) char dsmem[];
    uint32_t sbase = smem_u32(dsmem);

    const int tid  = threadIdx.x;
    const int lane = tid & 31;
    const int warp = tid >> 5;
    const int wm   = warp & 1;    // rows wm*64
    const int wn   = warp >> 1;   // cols wn*32
    const int m0   = blockIdx.x * 128;
    const int n0   = blockIdx.y * 128;

    float c[4][4][4];
    #pragma unroll
    for (int i = 0; i < 4; i++)
        #pragma unroll
        for (int j = 0; j < 4; j++)
            #pragma unroll
            for (int q = 0; q < 4; q++) c[i][j][q] = 0.f;

    const int NS = Kdim >> 5;   // K / 32

    auto load_stage = [&](int s, int buf) {
        int k0 = s * 32;
        uint32_t sb = sbase + buf * STG_B;
        #pragma unroll
        for (int it = 0; it < 8; it++) {
            int idx = tid + it * 256;          // 0..2047
            int mat = idx >> 9;                // 0 Ah, 1 Al, 2 Bh, 3 Bl
            int rem = idx & 511;
            int row = rem >> 2;
            int ch  = rem & 3;
            const __nv_bfloat16* g;
            if (mat == 0)      g = Ah + (size_t)(m0 + row) * Kdim;
            else if (mat == 1) g = Al + (size_t)(m0 + row) * Kdim;
            else if (mat == 2) g = Bh + (size_t)(n0 + row) * Kdim;
            else               g = Bl + (size_t)(n0 + row) * Kdim;
            cpa16(sb + mat * MAT_B + row * 80 + ch * 16, g + k0 + ch * 8);
        }
        asm volatile("cp.async.commit_group;" ::: "memory");
    };

    load_stage(0, 0);
    if (NS > 1) load_stage(1, 1);

    for (int s = 0; s < NS; s++) {
        if (s + 2 < NS) {
            load_stage(s + 2, (s + 2) % 3);
            asm volatile("cp.async.wait_group 2;" ::: "memory");
        } else if (s + 1 < NS) {
            asm volatile("cp.async.wait_group 1;" ::: "memory");
        } else {
            asm volatile("cp.async.wait_group 0;" ::: "memory");
        }
        __syncthreads();

        uint32_t sb = sbase + (s % 3) * STG_B;
        #pragma unroll
        for (int ks = 0; ks < 2; ks++) {
            // --- load all fragments for this k16 step ---
            uint32_t bh[2][4], bl[2][4];
            {
                int brow = wn * 32 + ((lane >> 4) << 3) + (lane & 7);
                int bk   = ks * 16 + ((lane >> 3) & 1) * 8;
                #pragma unroll
                for (int p = 0; p < 2; p++) {
                    uint32_t ab = sb + 2 * MAT_B + (brow + p * 16) * 80 + bk * 2;
                    LDSM_X4(bh[p][0], bh[p][1], bh[p][2], bh[p][3], ab);
                    LDSM_X4(bl[p][0], bl[p][1], bl[p][2], bl[p][3], ab + MAT_B);
                }
            }
            uint32_t ah[4][4], al[4][4];
            {
                int arow = wm * 64 + (lane & 15);
                int ak   = ks * 16 + (lane >> 4) * 8;
                #pragma unroll
                for (int mt = 0; mt < 4; mt++) {
                    uint32_t aa = sb + (arow + mt * 16) * 80 + ak * 2;
                    LDSM_X4(ah[mt][0], ah[mt][1], ah[mt][2], ah[mt][3], aa);
                    LDSM_X4(al[mt][0], al[mt][1], al[mt][2], al[mt][3], aa + MAT_B);
                }
            }
            // --- 48 MMAs grouped by term: 16 independent accumulators each ---
            #pragma unroll
            for (int mt = 0; mt < 4; mt++)
                #pragma unroll
                for (int nt = 0; nt < 4; nt++)
                    MMA_BF16(c[mt][nt], ah[mt],
                             bh[nt >> 1][(nt & 1) * 2], bh[nt >> 1][(nt & 1) * 2 + 1]);
            #pragma unroll
            for (int mt = 0; mt < 4; mt++)
                #pragma unroll
                for (int nt = 0; nt < 4; nt++)
                    MMA_BF16(c[mt][nt], al[mt],
                             bh[nt >> 1][(nt & 1) * 2], bh[nt >> 1][(nt & 1) * 2 + 1]);
            #pragma unroll
            for (int mt = 0; mt < 4; mt++)
                #pragma unroll
                for (int nt = 0; nt < 4; nt++)
                    MMA_BF16(c[mt][nt], ah[mt],
                             bl[nt >> 1][(nt & 1) * 2], bl[nt >> 1][(nt & 1) * 2 + 1]);
        }
        __syncthreads();
    }

    // epilogue
    const int mw = m0 + wm * 64;
    const int nw = n0 + wn * 32;
    #pragma unroll
    for (int mt = 0; mt < 4; mt++) {
        int r = mw + mt * 16 + (lane >> 2);
        #pragma unroll
        for (int nt = 0; nt < 4; nt++) {
            int cc = nw + nt * 8 + (lane & 3) * 2;
            float bx = bias[cc], by = bias[cc + 1];
            float2 v0 = { c[mt][nt][0] + bx, c[mt][nt][1] + by };
            float2 v1 = { c[mt][nt][2] + bx, c[mt][nt][3] + by };
            *reinterpret_cast<float2*>(C + (size_t)r * Nld + cc)       = v0;
            *reinterpret_cast<float2*>(C + (size_t)(r + 8) * Nld + cc) = v1;
        }
    }
}

// ---------------- fp32 -> bf16 hi/lo split -----------------------------------
__global__ void k_split(const float* __restrict__ x,
                        __nv_bfloat16* __restrict__ hi,
                        __nv_bfloat16* __restrict__ lo, int n4)
{
    int i = blockIdx.x * 256 + threadIdx.x;
    if (i >= n4) return;
    float4 v = reinterpret_cast<const float4*>(x)[i];
    __nv_bfloat16 h0 = __float2bfloat16(v.x);
    __nv_bfloat16 h1 = __float2bfloat16(v.y);
    __nv_bfloat16 h2 = __float2bfloat16(v.z);
    __nv_bfloat16 h3 = __float2bfloat16(v.w);
    __nv_bfloat16 l0 = __float2bfloat16(v.x - __bfloat162float(h0));
    __nv_bfloat16 l1 = __float2bfloat16(v.y - __bfloat162float(h1));
    __nv_bfloat16 l2 = __float2bfloat16(v.z - __bfloat162float(h2));
    __nv_bfloat16 l3 = __float2bfloat16(v.w - __bfloat162float(h3));
    __nv_bfloat162 hp0 = {h0, h1}, hp1 = {h2, h3};
    __nv_bfloat162 lp0 = {l0, l1}, lp1 = {l2, l3};
    reinterpret_cast<__nv_bfloat162*>(hi)[i * 2 + 0] = hp0;
    reinterpret_cast<__nv_bfloat162*>(hi)[i * 2 + 1] = hp1;
    reinterpret_cast<__nv_bfloat162*>(lo)[i * 2 + 0] = lp0;
    reinterpret_cast<__nv_bfloat162*>(lo)[i * 2 + 1] = lp1;
}

// ---------------- embedding gather -------------------------------------------
__global__ void k_embed(const int* __restrict__ word, const float* __restrict__ emb)
{
    int row = blockIdx.x;
    int w = word[row];
    const float4* src = reinterpret_cast<const float4*>(emb + (size_t)w * E);
    float4* dst = reinterpret_cast<float4*>(g_embeds + (size_t)row * E);
    dst[threadIdx.x] = src[threadIdx.x];
}

// ---------------- 1024x1024 transpose ----------------------------------------
__global__ void k_transpose(const float* __restrict__ W, float* __restrict__ WT)
{
    __shared__ float tile[32][33];
    int kx = blockIdx.x * 32 + threadIdx.x;
    int h0 = blockIdx.y * 32;
    #pragma unroll
    for (int j = threadIdx.y; j < 32; j += 8)
        tile[j][threadIdx.x] = W[(size_t)(h0 + j) * H + kx];
    __syncthreads();
    int ho = blockIdx.y * 32 + threadIdx.x;
    int k0 = blockIdx.x * 32;
    #pragma unroll
    for (int j = threadIdx.y; j < 32; j += 8)
        WT[(size_t)(k0 + j) * H + ho] = tile[threadIdx.x][j];
}

// ---------------- fused recurrence step --------------------------------------
// grid (16 htiles, 8 kchunks, 2 gates), 256 threads.
// Each block: partial gate preact over its k-chunk of 128, all 32 b.
// Last-arriving block per htile reduces (fixed order) + sigmoid + state update.
__global__ void __launch_bounds__(256) k_rstep(int parity, int t, int layer,
                                               float* __restrict__ out_ig,
                                               float* __restrict__ out_fg)
{
    const float* lat = parity ? g_latB : g_latA;
    const float* WT;
    if (layer == 0) WT = blockIdx.z ? g_WhfT  : g_WhiT;
    else            WT = blockIdx.z ? g_Whf2T : g_Whi2T;
    int ht = blockIdx.x;
    int h0 = ht * 64;
    int kcb = blockIdx.y;
    int tid = threadIdx.x;
    int hh = tid & 63, bq = tid >> 6;

    __shared__ float sLat[32][68];
    __shared__ float sW[64][64];

    float acc[8] = {0,0,0,0,0,0,0,0};
    #pragma unroll
    for (int sub = 0; sub < 2; sub++) {
        int k0 = kcb * 128 + sub * 64;
        #pragma unroll
        for (int i = tid; i < 512; i += 256) {
            int b = i >> 4, k4 = i & 15;
            float4 v = *reinterpret_cast<const float4*>(lat + b * H + k0 + k4 * 4);
            *reinterpret_cast<float4*>(&sLat[b][k4 * 4]) = v;
        }
        #pragma unroll
        for (int i = tid; i < 1024; i += 256) {
            int k = i >> 4, h4 = i & 15;
            float4 v = *reinterpret_cast<const float4*>(WT + (size_t)(k0 + k) * H + h0 + h4 * 4);
            *reinterpret_cast<float4*>(&sW[k][h4 * 4]) = v;
        }
        __syncthreads();
        #pragma unroll
        for (int k = 0; k < 64; k += 4) {
            float w0 = sW[k][hh], w1 = sW[k+1][hh], w2 = sW[k+2][hh], w3 = sW[k+3][hh];
            #pragma unroll
            for (int j = 0; j < 8; j++) {
                float4 l = *reinterpret_cast<const float4*>(&sLat[bq*8 + j][k]);
                acc[j] += l.x*w0 + l.y*w1 + l.z*w2 + l.w*w3;
            }
        }
        __syncthreads();
    }
    {
        float* p = g_part + ((size_t)(blockIdx.z * 8 + kcb) * 32) * H + h0 + hh;
        #pragma unroll
        for (int j = 0; j < 8; j++) p[(size_t)(bq*8 + j) * H] = acc[j];
    }
    __threadfence();
    __shared__ unsigned last;
    if (tid == 0)
        last = atomicAdd(&g_cnt[(layer * S + t) * 16 + ht], 1u);
    __syncthreads();
    if (last != 15) return;

    // --- this is the 16th block for this htile: reduce + update ---
    float* latN    = parity ? g_latA : g_latB;
    const float* x = layer ? g_l1 : g_embeds;
    float* lout    = layer ? g_embeds : g_l1;
    for (int i = tid; i < 2048; i += 256) {
        int b = i >> 6, h = h0 + (i & 63);
        int idx = b * H + h;
        float si = 0.f, sf = 0.f;
        #pragma unroll
        for (int kc = 0; kc < 8; kc++) {
            si += g_part[((size_t)kc * 32 + b) * H + h];
            sf += g_part[((size_t)(8 + kc) * 32 + b) * H + h];
        }
        size_t o = (size_t)t * BH + idx;
        float ig = 1.f / (1.f + expf(-(si + g_xi[o])));
        float fg = 1.f / (1.f + expf(-(sf + g_xf[o])));
        float ln = ig * x[o] + fg * lat[idx];
        latN[idx] = ln;
        lout[o]   = ln;
        if (out_ig) { out_ig[idx] = ig; out_fg[idx] = fg; }
    }
}

// -----------------------------------------------------------------------------
extern "C" void kernel_launch(void* const* d_in, const int* in_sizes, int n_in,
                              void* d_out, int out_size)
{
    (void)in_sizes; (void)n_in; (void)out_size;
    const int*   word   = (const int*)  d_in[0];
    const float* latent = (const float*)d_in[1];
    const float* emb    = (const float*)d_in[2];
    const float* h2o_w  = (const float*)d_in[3];
    const float* h2o_b  = (const float*)d_in[4];
    const float* Whi    = (const float*)d_in[5];
    const float* Wxi_w  = (const float*)d_in[6];
    const float* Wxi_b  = (const float*)d_in[7];
    const float* Whf    = (const float*)d_in[8];
    const float* Wxf_w  = (const float*)d_in[9];
    const float* Wxf_b  = (const float*)d_in[10];
    const float* Whi2   = (const float*)d_in[11];
    const float* Wxi2_w = (const float*)d_in[12];
    const float* Wxi2_b = (const float*)d_in[13];
    const float* Whf2   = (const float*)d_in[14];
    const float* Wxf2_w = (const float*)d_in[15];
    const float* Wxf2_b = (const float*)d_in[16];
    float* out = (float*)d_out;

    float *p_embeds, *p_xi, *p_xf, *p_l1, *p_latA;
    float *p_WhiT, *p_WhfT, *p_Whi2T, *p_Whf2T;
    __nv_bfloat16 *p_Ah, *p_Al, *p_Bh, *p_Bl;
    unsigned* p_cnt;
    cudaGetSymbolAddress((void**)&p_embeds, g_embeds);
    cudaGetSymbolAddress((void**)&p_xi,     g_xi);
    cudaGetSymbolAddress((void**)&p_xf,     g_xf);
    cudaGetSymbolAddress((void**)&p_l1,     g_l1);
    cudaGetSymbolAddress((void**)&p_latA,   g_latA);
    cudaGetSymbolAddress((void**)&p_WhiT,   g_WhiT);
    cudaGetSymbolAddress((void**)&p_WhfT,   g_WhfT);
    cudaGetSymbolAddress((void**)&p_Whi2T,  g_Whi2T);
    cudaGetSymbolAddress((void**)&p_Whf2T,  g_Whf2T);
    cudaGetSymbolAddress((void**)&p_Ah,     g_Ah);
    cudaGetSymbolAddress((void**)&p_Al,     g_Al);
    cudaGetSymbolAddress((void**)&p_Bh,     g_Bh);
    cudaGetSymbolAddress((void**)&p_Bl,     g_Bl);
    cudaGetSymbolAddress((void**)&p_cnt,    g_cnt);

    cudaFuncSetAttribute(k_hmma, cudaFuncAttributeMaxDynamicSharedMemorySize,
                         GEMM_SMEM);

    const size_t OUT_LOG = BH;
    const size_t OUT_IG  = BH + (size_t)SB * V;
    const size_t OUT_FG  = OUT_IG + BH;

    cudaMemsetAsync(p_cnt, 0, 2 * S * 16 * sizeof(unsigned));

    dim3 tgrid(32, 32), tblk(32, 8);
    k_transpose<<<tgrid, tblk>>>(Whi,  p_WhiT);
    k_transpose<<<tgrid, tblk>>>(Whf,  p_WhfT);
    k_transpose<<<tgrid, tblk>>>(Whi2, p_Whi2T);
    k_transpose<<<tgrid, tblk>>>(Whf2, p_Whf2T);

    k_embed<<<SB, 256>>>(word, emb);

    const int ACT4 = SB * H / 4;   // 1048576
    const int W4   = H * H / 4;    // 262144
    const int HO4  = V * H / 4;    // 8192000

    // layer-1 input gate preactivations via tensor cores
    k_split<<<ACT4/256, 256>>>(p_embeds, p_Ah, p_Al, ACT4);
    dim3 ggrid(SB/128, H/128);     // (32, 8)
    k_split<<<W4/256, 256>>>(Wxi_w, p_Bh, p_Bl, W4);
    k_hmma<<<ggrid, 256, GEMM_SMEM>>>(p_Ah, p_Al, p_Bh, p_Bl, Wxi_b, p_xi, H, H);
    k_split<<<W4/256, 256>>>(Wxf_w, p_Bh, p_Bl, W4);
    k_hmma<<<ggrid, 256, GEMM_SMEM>>>(p_Ah, p_Al, p_Bh, p_Bl, Wxf_b, p_xf, H, H);

    cudaMemcpyAsync(p_latA, latent, (size_t)BH * sizeof(float),
                    cudaMemcpyDeviceToDevice);

    dim3 rgrid(16, 8, 2);
    for (int t = 0; t < S; t++)
        k_rstep<<<rgrid, 256>>>(t & 1, t, 0, nullptr, nullptr);

    // layer-2 input gate preactivations
    k_split<<<ACT4/256, 256>>>(p_l1, p_Ah, p_Al, ACT4);
    k_split<<<W4/256, 256>>>(Wxi2_w, p_Bh, p_Bl, W4);
    k_hmma<<<ggrid, 256, GEMM_SMEM>>>(p_Ah, p_Al, p_Bh, p_Bl, Wxi2_b, p_xi, H, H);
    k_split<<<W4/256, 256>>>(Wxf2_w, p_Bh, p_Bl, W4);
    k_hmma<<<ggrid, 256, GEMM_SMEM>>>(p_Ah, p_Al, p_Bh, p_Bl, Wxf2_b, p_xf, H, H);

    for (int t = 0; t < S; t++) {
        float* oig = (t == S-1) ? out + OUT_IG : nullptr;
        float* ofg = (t == S-1) ? out + OUT_FG : nullptr;
        k_rstep<<<rgrid, 256>>>(t & 1, t, 1, oig, ofg);
    }

    // logits: [4096,1024] x [32000,1024]^T + bias via tensor cores
    k_split<<<ACT4/256, 256>>>(p_embeds /* = l2_out */, p_Ah, p_Al, ACT4);
    k_split<<<HO4/256, 256>>>(h2o_w, p_Bh, p_Bl, HO4);
    dim3 lgrid(SB/128, V/128);     // (32, 250)
    k_hmma<<<lgrid, 256, GEMM_SMEM>>>(p_Ah, p_Al, p_Bh, p_Bl, h2o_b,
                                      out + OUT_LOG, H, V);

    cudaMemcpyAsync(out, p_latA, (size_t)BH * sizeof(float),
                    cudaMemcpyDeviceToDevice);
}

// round 5
// speedup vs baseline: 1.5565x; 1.5565x over previous
#include <cuda_runtime.h>
#include <cuda_bf16.h>
#include <math.h>
#include <stdint.h>

#define S 128
#define B 32
#define H 1024
#define E 1024
#define V 32000
#define SB (S*B)        /* 4096  */
#define BH (B*H)        /* 32768 */

// ---------------- scratch (device globals; no allocations allowed) ----------
__device__ float g_embeds[SB*H];   // embeds for layer1, reused as l2_out
__device__ float g_xi[SB*H];
__device__ float g_xf[SB*H];
__device__ float g_l1[SB*H];
__device__ float g_latA[BH];
__device__ float g_latB[BH];
__device__ float g_part[2*16*B*H];
__device__ float g_WhiT[H*H];
__device__ float g_WhfT[H*H];
__device__ float g_Whi2T[H*H];
__device__ float g_Whf2T[H*H];
// bf16 split operands for tensor-core GEMMs
__device__ __nv_bfloat16 g_Ah[SB*H];
__device__ __nv_bfloat16 g_Al[SB*H];
__device__ __nv_bfloat16 g_Bh[(size_t)V*H];
__device__ __nv_bfloat16 g_Bl[(size_t)V*H];

// ============================ helpers ========================================
__device__ __forceinline__ uint32_t smem_u32(const void* p) {
    uint32_t a;
    asm("{ .reg .u64 t; cvta.to.shared.u64 t, %1; cvt.u32.u64 %0, t; }"
        : "=r"(a) : "l"(p));
    return a;
}
__device__ __forceinline__ void cpa16(uint32_t s, const void* g) {
    asm volatile("cp.async.cg.shared.global [%0], [%1], 16;" :: "r"(s), "l"(g) : "memory");
}
#define LDSM_X4(r0,r1,r2,r3,addr) \
    asm volatile("ldmatrix.sync.aligned.m8n8.x4.shared.b16 {%0,%1,%2,%3}, [%4];" \
        : "=r"(r0),"=r"(r1),"=r"(r2),"=r"(r3) : "r"(addr))
#define MMA_BF16(c, a, b0, b1) \
    asm volatile("mma.sync.aligned.m16n8k16.row.col.f32.bf16.bf16.f32 " \
        "{%0,%1,%2,%3}, {%4,%5,%6,%7}, {%8,%9}, {%0,%1,%2,%3};" \
        : "+f"((c)[0]),"+f"((c)[1]),"+f"((c)[2]),"+f"((c)[3]) \
        : "r"((a)[0]),"r"((a)[1]),"r"((a)[2]),"r"((a)[3]), "r"(b0),"r"(b1))

// ================= split-bf16 HMMA GEMM ======================================
// C[M,Nld](fp32) = Ah*Bh^T + Al*Bh^T + Ah*Bl^T + bias
// block tile 128x128, BK=32, 256 threads (warps 2M x 4N, warp tile 64x32).
// smem rows padded to 80B -> conflict-free ldmatrix, no swizzle.
// 2 CTAs/SM (160KB smem) for cross-CTA latency hiding.
#define ROWP 40                      /* bf16 elems per smem row (80B) */
#define MAT_B (128*ROWP*2)           /* 10240 bytes per matrix tile   */
#define STG_B (4*MAT_B)              /* 40960 bytes per stage         */
#define GEMM_SMEM (2*STG_B)          /* 81920                         */

__global__ void __launch_bounds__(256, 2)
k_hmma(const __nv_bfloat16* __restrict__ Ah, const __nv_bfloat16* __restrict__ Al,
       const __nv_bfloat16* __restrict__ Bh, const __nv_bfloat16* __restrict__ Bl,
       const float* __restrict__ bias, float* __restrict__ C,
       int Kdim, int Nld)
{
    extern __shared__ __align__(16) char dsmem[];
    uint32_t sbase = smem_u32(dsmem);

    const int tid  = threadIdx.x;
    const int lane = tid & 31;
    const int warp = tid >> 5;
    const int wm   = warp & 1;    // 0..1  -> rows wm*64
    const int wn   = warp >> 1;   // 0..3  -> cols wn*32
    const int m0   = blockIdx.x * 128;
    const int n0   = blockIdx.y * 128;

    float c[4][4][4];
    #pragma unroll
    for (int i = 0; i < 4; i++)
        #pragma unroll
        for (int j = 0; j < 4; j++)
            #pragma unroll
            for (int q = 0; q < 4; q++) c[i][j][q] = 0.f;

    const int NS = Kdim >> 5;   // K / 32

    // stage loader: 4 matrices x 128 rows x 32 bf16 (4x16B chunks per row)
    auto load_stage = [&](int s, int buf) {
        int k0 = s * 32;
        uint32_t sb = sbase + buf * STG_B;
        #pragma unroll
        for (int it = 0; it < 8; it++) {
            int idx = tid + it * 256;          // 0..2047
            int mat = idx >> 9;                // 0 Ah, 1 Al, 2 Bh, 3 Bl
            int rem = idx & 511;
            int row = rem >> 2;
            int ch  = rem & 3;
            const __nv_bfloat16* g;
            if (mat == 0)      g = Ah + (size_t)(m0 + row) * Kdim;
            else if (mat == 1) g = Al + (size_t)(m0 + row) * Kdim;
            else if (mat == 2) g = Bh + (size_t)(n0 + row) * Kdim;
            else               g = Bl + (size_t)(n0 + row) * Kdim;
            cpa16(sb + mat * MAT_B + row * 80 + ch * 16, g + k0 + ch * 8);
        }
        asm volatile("cp.async.commit_group;" ::: "memory");
    };

    load_stage(0, 0);

    for (int s = 0; s < NS; s++) {
        int buf = s & 1;
        if (s + 1 < NS) {
            load_stage(s + 1, (s + 1) & 1);
            asm volatile("cp.async.wait_group 1;" ::: "memory");
        } else {
            asm volatile("cp.async.wait_group 0;" ::: "memory");
        }
        __syncthreads();

        uint32_t sb = sbase + buf * STG_B;
        #pragma unroll
        for (int ks = 0; ks < 2; ks++) {
            // B fragments: 2 x ldmatrix.x4 per matrix (covers n32 k16)
            uint32_t bh[2][4], bl[2][4];
            {
                int brow = wn * 32 + ((lane >> 4) << 3) + (lane & 7);
                int bk   = ks * 16 + ((lane >> 3) & 1) * 8;
                #pragma unroll
                for (int p = 0; p < 2; p++) {
                    uint32_t ab = sb + 2 * MAT_B + (brow + p * 16) * 80 + bk * 2;
                    LDSM_X4(bh[p][0], bh[p][1], bh[p][2], bh[p][3], ab);
                    LDSM_X4(bl[p][0], bl[p][1], bl[p][2], bl[p][3], ab + MAT_B);
                }
            }
            int arow = wm * 64 + (lane & 15);
            int ak   = ks * 16 + (lane >> 4) * 8;
            #pragma unroll
            for (int mt = 0; mt < 4; mt++) {
                uint32_t aa = sb + (arow + mt * 16) * 80 + ak * 2;
                uint32_t ah[4], al[4];
                LDSM_X4(ah[0], ah[1], ah[2], ah[3], aa);
                LDSM_X4(al[0], al[1], al[2], al[3], aa + MAT_B);
                #pragma unroll
                for (int p = 0; p < 2; p++) {
                    #pragma unroll
                    for (int hf = 0; hf < 2; hf++) {
                        int nt = p * 2 + hf;
                        uint32_t b0h = bh[p][hf*2], b1h = bh[p][hf*2+1];
                        uint32_t b0l = bl[p][hf*2], b1l = bl[p][hf*2+1];
                        MMA_BF16(c[mt][nt], ah, b0h, b1h);
                        MMA_BF16(c[mt][nt], al, b0h, b1h);
                        MMA_BF16(c[mt][nt], ah, b0l, b1l);
                    }
                }
            }
        }
        __syncthreads();
    }

    // epilogue
    const int mw = m0 + wm * 64;
    const int nw = n0 + wn * 32;
    #pragma unroll
    for (int mt = 0; mt < 4; mt++) {
        int r = mw + mt * 16 + (lane >> 2);
        #pragma unroll
        for (int nt = 0; nt < 4; nt++) {
            int cc = nw + nt * 8 + (lane & 3) * 2;
            float bx = bias[cc], by = bias[cc + 1];
            float2 v0 = { c[mt][nt][0] + bx, c[mt][nt][1] + by };
            float2 v1 = { c[mt][nt][2] + bx, c[mt][nt][3] + by };
            *reinterpret_cast<float2*>(C + (size_t)r * Nld + cc)       = v0;
            *reinterpret_cast<float2*>(C + (size_t)(r + 8) * Nld + cc) = v1;
        }
    }
}

// ---------------- fp32 -> bf16 hi/lo split -----------------------------------
__global__ void k_split(const float* __restrict__ x,
                        __nv_bfloat16* __restrict__ hi,
                        __nv_bfloat16* __restrict__ lo, int n4)
{
    int i = blockIdx.x * 256 + threadIdx.x;
    if (i >= n4) return;
    float4 v = reinterpret_cast<const float4*>(x)[i];
    __nv_bfloat16 h0 = __float2bfloat16(v.x);
    __nv_bfloat16 h1 = __float2bfloat16(v.y);
    __nv_bfloat16 h2 = __float2bfloat16(v.z);
    __nv_bfloat16 h3 = __float2bfloat16(v.w);
    __nv_bfloat16 l0 = __float2bfloat16(v.x - __bfloat162float(h0));
    __nv_bfloat16 l1 = __float2bfloat16(v.y - __bfloat162float(h1));
    __nv_bfloat16 l2 = __float2bfloat16(v.z - __bfloat162float(h2));
    __nv_bfloat16 l3 = __float2bfloat16(v.w - __bfloat162float(h3));
    __nv_bfloat162 hp0 = {h0, h1}, hp1 = {h2, h3};
    __nv_bfloat162 lp0 = {l0, l1}, lp1 = {l2, l3};
    reinterpret_cast<__nv_bfloat162*>(hi)[i * 2 + 0] = hp0;
    reinterpret_cast<__nv_bfloat162*>(hi)[i * 2 + 1] = hp1;
    reinterpret_cast<__nv_bfloat162*>(lo)[i * 2 + 0] = lp0;
    reinterpret_cast<__nv_bfloat162*>(lo)[i * 2 + 1] = lp1;
}

// ---------------- embedding gather -------------------------------------------
__global__ void k_embed(const int* __restrict__ word, const float* __restrict__ emb)
{
    int row = blockIdx.x;
    int w = word[row];
    const float4* src = reinterpret_cast<const float4*>(emb + (size_t)w * E);
    float4* dst = reinterpret_cast<float4*>(g_embeds + (size_t)row * E);
    dst[threadIdx.x] = src[threadIdx.x];
}

// ---------------- 1024x1024 transpose ----------------------------------------
__global__ void k_transpose(const float* __restrict__ W, float* __restrict__ WT)
{
    __shared__ float tile[32][33];
    int kx = blockIdx.x * 32 + threadIdx.x;
    int h0 = blockIdx.y * 32;
    #pragma unroll
    for (int j = threadIdx.y; j < 32; j += 8)
        tile[j][threadIdx.x] = W[(size_t)(h0 + j) * H + kx];
    __syncthreads();
    int ho = blockIdx.y * 32 + threadIdx.x;
    int k0 = blockIdx.x * 32;
    #pragma unroll
    for (int j = threadIdx.y; j < 32; j += 8)
        WT[(size_t)(k0 + j) * H + ho] = tile[threadIdx.x][j];
}

// ---------------- recurrence: gate partial GEMM -------------------------------
__global__ void __launch_bounds__(256) k_r1(int parity, int layer)
{
    const float* lat = parity ? g_latB : g_latA;
    const float* WT;
    if (layer == 0) WT = blockIdx.z ? g_WhfT  : g_WhiT;
    else            WT = blockIdx.z ? g_Whf2T : g_Whi2T;
    int h0 = blockIdx.x * 64;
    int k0 = blockIdx.y * 64;

    __shared__ float sLat[32][68];
    __shared__ float sW[64][64];

    int tid = threadIdx.x;
    #pragma unroll
    for (int i = tid; i < 512; i += 256) {
        int b = i >> 4, k4 = i & 15;
        float4 v = *reinterpret_cast<const float4*>(lat + b * H + k0 + k4 * 4);
        *reinterpret_cast<float4*>(&sLat[b][k4 * 4]) = v;
    }
    #pragma unroll
    for (int i = tid; i < 1024; i += 256) {
        int k = i >> 4, h4 = i & 15;
        float4 v = *reinterpret_cast<const float4*>(WT + (size_t)(k0 + k) * H + h0 + h4 * 4);
        *reinterpret_cast<float4*>(&sW[k][h4 * 4]) = v;
    }
    __syncthreads();

    int hh = tid & 63, bq = tid >> 6;
    float acc[8] = {0,0,0,0,0,0,0,0};
    #pragma unroll
    for (int k = 0; k < 64; k += 4) {
        float w0 = sW[k][hh], w1 = sW[k+1][hh], w2 = sW[k+2][hh], w3 = sW[k+3][hh];
        #pragma unroll
        for (int j = 0; j < 8; j++) {
            float4 l = *reinterpret_cast<const float4*>(&sLat[bq*8 + j][k]);
            acc[j] += l.x*w0 + l.y*w1 + l.z*w2 + l.w*w3;
        }
    }
    float* p = g_part + ((size_t)(blockIdx.z * 16 + blockIdx.y) * 32) * H + h0 + hh;
    #pragma unroll
    for (int j = 0; j < 8; j++) p[(size_t)(bq*8 + j) * H] = acc[j];
}

// ---------------- recurrence: reduce + sigmoid + update -----------------------
__global__ void k_r2(int parity, int t, int layer,
                     float* __restrict__ out_ig, float* __restrict__ out_fg)
{
    int idx = blockIdx.x * 256 + threadIdx.x;
    int b = idx >> 10;
    const float* latO = parity ? g_latB : g_latA;
    float* latN       = parity ? g_latA : g_latB;

    float si = 0.f, sf = 0.f;
    #pragma unroll
    for (int kc = 0; kc < 16; kc++) {
        si += g_part[((size_t)kc * 32 + b) * H + (idx & 1023)];
        sf += g_part[((size_t)(16 + kc) * 32 + b) * H + (idx & 1023)];
    }
    size_t o = (size_t)t * BH + idx;
    float pi = si + g_xi[o];
    float pf = sf + g_xf[o];
    float ig = 1.f / (1.f + expf(-pi));
    float fg = 1.f / (1.f + expf(-pf));
    const float* x = layer ? g_l1 : g_embeds;
    float* lout    = layer ? g_embeds : g_l1;
    float ln = ig * x[o] + fg * latO[idx];
    latN[idx] = ln;
    lout[o]   = ln;
    if (out_ig) { out_ig[idx] = ig; out_fg[idx] = fg; }
}

// -----------------------------------------------------------------------------
extern "C" void kernel_launch(void* const* d_in, const int* in_sizes, int n_in,
                              void* d_out, int out_size)
{
    (void)in_sizes; (void)n_in; (void)out_size;
    const int*   word   = (const int*)  d_in[0];
    const float* latent = (const float*)d_in[1];
    const float* emb    = (const float*)d_in[2];
    const float* h2o_w  = (const float*)d_in[3];
    const float* h2o_b  = (const float*)d_in[4];
    const float* Whi    = (const float*)d_in[5];
    const float* Wxi_w  = (const float*)d_in[6];
    const float* Wxi_b  = (const float*)d_in[7];
    const float* Whf    = (const float*)d_in[8];
    const float* Wxf_w  = (const float*)d_in[9];
    const float* Wxf_b  = (const float*)d_in[10];
    const float* Whi2   = (const float*)d_in[11];
    const float* Wxi2_w = (const float*)d_in[12];
    const float* Wxi2_b = (const float*)d_in[13];
    const float* Whf2   = (const float*)d_in[14];
    const float* Wxf2_w = (const float*)d_in[15];
    const float* Wxf2_b = (const float*)d_in[16];
    float* out = (float*)d_out;

    float *p_embeds, *p_xi, *p_xf, *p_l1, *p_latA;
    float *p_WhiT, *p_WhfT, *p_Whi2T, *p_Whf2T;
    __nv_bfloat16 *p_Ah, *p_Al, *p_Bh, *p_Bl;
    cudaGetSymbolAddress((void**)&p_embeds, g_embeds);
    cudaGetSymbolAddress((void**)&p_xi,     g_xi);
    cudaGetSymbolAddress((void**)&p_xf,     g_xf);
    cudaGetSymbolAddress((void**)&p_l1,     g_l1);
    cudaGetSymbolAddress((void**)&p_latA,   g_latA);
    cudaGetSymbolAddress((void**)&p_WhiT,   g_WhiT);
    cudaGetSymbolAddress((void**)&p_WhfT,   g_WhfT);
    cudaGetSymbolAddress((void**)&p_Whi2T,  g_Whi2T);
    cudaGetSymbolAddress((void**)&p_Whf2T,  g_Whf2T);
    cudaGetSymbolAddress((void**)&p_Ah,     g_Ah);
    cudaGetSymbolAddress((void**)&p_Al,     g_Al);
    cudaGetSymbolAddress((void**)&p_Bh,     g_Bh);
    cudaGetSymbolAddress((void**)&p_Bl,     g_Bl);

    cudaFuncSetAttribute(k_hmma, cudaFuncAttributeMaxDynamicSharedMemorySize,
                         GEMM_SMEM);

    const size_t OUT_LOG = BH;
    const size_t OUT_IG  = BH + (size_t)SB * V;
    const size_t OUT_FG  = OUT_IG + BH;

    dim3 tgrid(32, 32), tblk(32, 8);
    k_transpose<<<tgrid, tblk>>>(Whi,  p_WhiT);
    k_transpose<<<tgrid, tblk>>>(Whf,  p_WhfT);
    k_transpose<<<tgrid, tblk>>>(Whi2, p_Whi2T);
    k_transpose<<<tgrid, tblk>>>(Whf2, p_Whf2T);

    k_embed<<<SB, 256>>>(word, emb);

    const int ACT4 = SB * H / 4;   // 1048576
    const int W4   = H * H / 4;    // 262144
    const int HO4  = V * H / 4;    // 8192000

    // layer-1 input gate preactivations via tensor cores
    k_split<<<ACT4/256, 256>>>(p_embeds, p_Ah, p_Al, ACT4);
    dim3 ggrid(SB/128, H/128);     // (32, 8)
    k_split<<<W4/256, 256>>>(Wxi_w, p_Bh, p_Bl, W4);
    k_hmma<<<ggrid, 256, GEMM_SMEM>>>(p_Ah, p_Al, p_Bh, p_Bl, Wxi_b, p_xi, H, H);
    k_split<<<W4/256, 256>>>(Wxf_w, p_Bh, p_Bl, W4);
    k_hmma<<<ggrid, 256, GEMM_SMEM>>>(p_Ah, p_Al, p_Bh, p_Bl, Wxf_b, p_xf, H, H);

    cudaMemcpyAsync(p_latA, latent, (size_t)BH * sizeof(float),
                    cudaMemcpyDeviceToDevice);

    dim3 rgrid(16, 16, 2);
    for (int t = 0; t < S; t++) {
        int parity = t & 1;
        k_r1<<<rgrid, 256>>>(parity, 0);
        k_r2<<<BH/256, 256>>>(parity, t, 0, nullptr, nullptr);
    }

    // layer-2 input gate preactivations
    k_split<<<ACT4/256, 256>>>(p_l1, p_Ah, p_Al, ACT4);
    k_split<<<W4/256, 256>>>(Wxi2_w, p_Bh, p_Bl, W4);
    k_hmma<<<ggrid, 256, GEMM_SMEM>>>(p_Ah, p_Al, p_Bh, p_Bl, Wxi2_b, p_xi, H, H);
    k_split<<<W4/256, 256>>>(Wxf2_w, p_Bh, p_Bl, W4);
    k_hmma<<<ggrid, 256, GEMM_SMEM>>>(p_Ah, p_Al, p_Bh, p_Bl, Wxf2_b, p_xf, H, H);

    for (int t = 0; t < S; t++) {
        int parity = t & 1;
        k_r1<<<rgrid, 256>>>(parity, 1);
        float* oig = (t == S-1) ? out + OUT_IG : nullptr;
        float* ofg = (t == S-1) ? out + OUT_FG : nullptr;
        k_r2<<<BH/256, 256>>>(parity, t, 1, oig, ofg);
    }

    // logits: [4096,1024] x [32000,1024]^T + bias via tensor cores
    k_split<<<ACT4/256, 256>>>(p_embeds /* = l2_out */, p_Ah, p_Al, ACT4);
    k_split<<<HO4/256, 256>>>(h2o_w, p_Bh, p_Bl, HO4);
    dim3 lgrid(SB/128, V/128);     // (32, 250)
    k_hmma<<<lgrid, 256, GEMM_SMEM>>>(p_Ah, p_Al, p_Bh, p_Bl, h2o_b,
                                      out + OUT_LOG, H, V);

    cudaMemcpyAsync(out, p_latA, (size_t)BH * sizeof(float),
                    cudaMemcpyDeviceToDevice);
}

// round 6
// speedup vs baseline: 1.9580x; 1.2579x over previous
#include <cuda_runtime.h>
#include <cuda_bf16.h>
#include <math.h>
#include <stdint.h>

#define S 128
#define B 32
#define H 1024
#define E 1024
#define V 32000
#define SB (S*B)        /* 4096  */
#define BH (B*H)        /* 32768 */

// ---------------- scratch (device globals; no allocations allowed) ----------
__device__ float g_embeds[SB*H];   // embeds for layer1, reused as l2_out
__device__ float g_xi[SB*H];
__device__ float g_xf[SB*H];
__device__ float g_l1[SB*H];
__device__ float g_lat[BH];                    // fp32 latent state
__device__ __nv_bfloat16 g_latH[BH];
__device__ __nv_bfloat16 g_latL[BH];
__device__ float g_part2[2*8*B*H];             // [gate][kt][b][h]
__device__ unsigned g_bar[2];                  // per-layer barrier counters
// recurrent weights, bf16 split: [mat 0..3][n=h_out][k=h_in]
__device__ __nv_bfloat16 g_WgH[4*H*H];
__device__ __nv_bfloat16 g_WgL[4*H*H];
// bf16 split operands for tensor-core GEMMs
__device__ __nv_bfloat16 g_Ah[SB*H];
__device__ __nv_bfloat16 g_Al[SB*H];
__device__ __nv_bfloat16 g_Bh[(size_t)V*H];
__device__ __nv_bfloat16 g_Bl[(size_t)V*H];

// ============================ helpers ========================================
__device__ __forceinline__ uint32_t smem_u32(const void* p) {
    uint32_t a;
    asm("{ .reg .u64 t; cvta.to.shared.u64 t, %1; cvt.u32.u64 %0, t; }"
        : "=r"(a) : "l"(p));
    return a;
}
__device__ __forceinline__ void cpa16(uint32_t s, const void* g) {
    asm volatile("cp.async.cg.shared.global [%0], [%1], 16;" :: "r"(s), "l"(g) : "memory");
}
__device__ __forceinline__ unsigned ldcg_u32(const unsigned* p) {
    unsigned v;
    asm volatile("ld.global.cg.u32 %0, [%1];" : "=r"(v) : "l"(p));
    return v;
}
#define LDSM_X4(r0,r1,r2,r3,addr) \
    asm volatile("ldmatrix.sync.aligned.m8n8.x4.shared.b16 {%0,%1,%2,%3}, [%4];" \
        : "=r"(r0),"=r"(r1),"=r"(r2),"=r"(r3) : "r"(addr))
#define MMA_BF16(c, a, b0, b1) \
    asm volatile("mma.sync.aligned.m16n8k16.row.col.f32.bf16.bf16.f32 " \
        "{%0,%1,%2,%3}, {%4,%5,%6,%7}, {%8,%9}, {%0,%1,%2,%3};" \
        : "+f"((c)[0]),"+f"((c)[1]),"+f"((c)[2]),"+f"((c)[3]) \
        : "r"((a)[0]),"r"((a)[1]),"r"((a)[2]),"r"((a)[3]), "r"(b0),"r"(b1))

// ================= split-bf16 HMMA GEMM (unchanged R5 winner) ================
#define ROWP 40
#define MAT_B (128*ROWP*2)
#define STG_B (4*MAT_B)
#define GEMM_SMEM (2*STG_B)

__global__ void __launch_bounds__(256, 2)
k_hmma(const __nv_bfloat16* __restrict__ Ah, const __nv_bfloat16* __restrict__ Al,
       const __nv_bfloat16* __restrict__ Bh, const __nv_bfloat16* __restrict__ Bl,
       const float* __restrict__ bias, float* __restrict__ C,
       int Kdim, int Nld)
{
    extern __shared__ __align__(16) char dsmem[];
    uint32_t sbase = smem_u32(dsmem);

    const int tid  = threadIdx.x;
    const int lane = tid & 31;
    const int warp = tid >> 5;
    const int wm   = warp & 1;
    const int wn   = warp >> 1;
    const int m0   = blockIdx.x * 128;
    const int n0   = blockIdx.y * 128;

    float c[4][4][4];
    #pragma unroll
    for (int i = 0; i < 4; i++)
        #pragma unroll
        for (int j = 0; j < 4; j++)
            #pragma unroll
            for (int q = 0; q < 4; q++) c[i][j][q] = 0.f;

    const int NS = Kdim >> 5;

    auto load_stage = [&](int s, int buf) {
        int k0 = s * 32;
        uint32_t sb = sbase + buf * STG_B;
        #pragma unroll
        for (int it = 0; it < 8; it++) {
            int idx = tid + it * 256;
            int mat = idx >> 9;
            int rem = idx & 511;
            int row = rem >> 2;
            int ch  = rem & 3;
            const __nv_bfloat16* g;
            if (mat == 0)      g = Ah + (size_t)(m0 + row) * Kdim;
            else if (mat == 1) g = Al + (size_t)(m0 + row) * Kdim;
            else if (mat == 2) g = Bh + (size_t)(n0 + row) * Kdim;
            else               g = Bl + (size_t)(n0 + row) * Kdim;
            cpa16(sb + mat * MAT_B + row * 80 + ch * 16, g + k0 + ch * 8);
        }
        asm volatile("cp.async.commit_group;" ::: "memory");
    };

    load_stage(0, 0);

    for (int s = 0; s < NS; s++) {
        int buf = s & 1;
        if (s + 1 < NS) {
            load_stage(s + 1, (s + 1) & 1);
            asm volatile("cp.async.wait_group 1;" ::: "memory");
        } else {
            asm volatile("cp.async.wait_group 0;" ::: "memory");
        }
        __syncthreads();

        uint32_t sb = sbase + buf * STG_B;
        #pragma unroll
        for (int ks = 0; ks < 2; ks++) {
            uint32_t bh[2][4], bl[2][4];
            {
                int brow = wn * 32 + ((lane >> 4) << 3) + (lane & 7);
                int bk   = ks * 16 + ((lane >> 3) & 1) * 8;
                #pragma unroll
                for (int p = 0; p < 2; p++) {
                    uint32_t ab = sb + 2 * MAT_B + (brow + p * 16) * 80 + bk * 2;
                    LDSM_X4(bh[p][0], bh[p][1], bh[p][2], bh[p][3], ab);
                    LDSM_X4(bl[p][0], bl[p][1], bl[p][2], bl[p][3], ab + MAT_B);
                }
            }
            int arow = wm * 64 + (lane & 15);
            int ak   = ks * 16 + (lane >> 4) * 8;
            #pragma unroll
            for (int mt = 0; mt < 4; mt++) {
                uint32_t aa = sb + (arow + mt * 16) * 80 + ak * 2;
                uint32_t ah[4], al[4];
                LDSM_X4(ah[0], ah[1], ah[2], ah[3], aa);
                LDSM_X4(al[0], al[1], al[2], al[3], aa + MAT_B);
                #pragma unroll
                for (int p = 0; p < 2; p++) {
                    #pragma unroll
                    for (int hf = 0; hf < 2; hf++) {
                        int nt = p * 2 + hf;
                        uint32_t b0h = bh[p][hf*2], b1h = bh[p][hf*2+1];
                        uint32_t b0l = bl[p][hf*2], b1l = bl[p][hf*2+1];
                        MMA_BF16(c[mt][nt], ah, b0h, b1h);
                        MMA_BF16(c[mt][nt], al, b0h, b1h);
                        MMA_BF16(c[mt][nt], ah, b0l, b1l);
                    }
                }
            }
        }
        __syncthreads();
    }

    const int mw = m0 + wm * 64;
    const int nw = n0 + wn * 32;
    #pragma unroll
    for (int mt = 0; mt < 4; mt++) {
        int r = mw + mt * 16 + (lane >> 2);
        #pragma unroll
        for (int nt = 0; nt < 4; nt++) {
            int cc = nw + nt * 8 + (lane & 3) * 2;
            float bx = bias[cc], by = bias[cc + 1];
            float2 v0 = { c[mt][nt][0] + bx, c[mt][nt][1] + by };
            float2 v1 = { c[mt][nt][2] + bx, c[mt][nt][3] + by };
            *reinterpret_cast<float2*>(C + (size_t)r * Nld + cc)       = v0;
            *reinterpret_cast<float2*>(C + (size_t)(r + 8) * Nld + cc) = v1;
        }
    }
}

// ---------------- fp32 -> bf16 hi/lo split -----------------------------------
__global__ void k_split(const float* __restrict__ x,
                        __nv_bfloat16* __restrict__ hi,
                        __nv_bfloat16* __restrict__ lo, int n4)
{
    int i = blockIdx.x * 256 + threadIdx.x;
    if (i >= n4) return;
    float4 v = reinterpret_cast<const float4*>(x)[i];
    __nv_bfloat16 h0 = __float2bfloat16(v.x);
    __nv_bfloat16 h1 = __float2bfloat16(v.y);
    __nv_bfloat16 h2 = __float2bfloat16(v.z);
    __nv_bfloat16 h3 = __float2bfloat16(v.w);
    __nv_bfloat16 l0 = __float2bfloat16(v.x - __bfloat162float(h0));
    __nv_bfloat16 l1 = __float2bfloat16(v.y - __bfloat162float(h1));
    __nv_bfloat16 l2 = __float2bfloat16(v.z - __bfloat162float(h2));
    __nv_bfloat16 l3 = __float2bfloat16(v.w - __bfloat162float(h3));
    __nv_bfloat162 hp0 = {h0, h1}, hp1 = {h2, h3};
    __nv_bfloat162 lp0 = {l0, l1}, lp1 = {l2, l3};
    reinterpret_cast<__nv_bfloat162*>(hi)[i * 2 + 0] = hp0;
    reinterpret_cast<__nv_bfloat162*>(hi)[i * 2 + 1] = hp1;
    reinterpret_cast<__nv_bfloat162*>(lo)[i * 2 + 0] = lp0;
    reinterpret_cast<__nv_bfloat162*>(lo)[i * 2 + 1] = lp1;
}

// ---------------- embedding gather -------------------------------------------
__global__ void k_embed(const int* __restrict__ word, const float* __restrict__ emb)
{
    int row = blockIdx.x;
    int w = word[row];
    const float4* src = reinterpret_cast<const float4*>(emb + (size_t)w * E);
    float4* dst = reinterpret_cast<float4*>(g_embeds + (size_t)row * E);
    dst[threadIdx.x] = src[threadIdx.x];
}

// ================= persistent recurrence (one launch per layer) ==============
// grid = 128 CTAs x 256 thr. CTA c: gate g=c>>6, nt=(c&63)>>3, kt=c&7.
// Weight slice [n0:n0+128][k0:k0+128] hi/lo cached in smem for all 128 steps.
// Per step: phase1 split-bf16 HMMA -> g_part2 ; barrier ; phase2 reduce+update.
#define RP 272                            /* smem row pitch bytes (17*16) */
#define W_HI 0
#define W_LO (128*RP)                     /* 34816 */
#define A_BASE (2*128*RP)                 /* 69632 */
#define A_LO (32*RP)                      /* 8704  */
#define RNN_SMEM (A_BASE + 2*32*RP)       /* 87040 */

__global__ void __launch_bounds__(256)
k_rnn(const float* __restrict__ lat0,
      const float* __restrict__ xi, const float* __restrict__ xf,
      const float* __restrict__ x, float* __restrict__ lout,
      const __nv_bfloat16* __restrict__ WH, const __nv_bfloat16* __restrict__ WL,
      unsigned* __restrict__ bar,
      float* __restrict__ out_ig, float* __restrict__ out_fg)
{
    extern __shared__ __align__(16) char dsmem[];
    uint32_t sb = smem_u32(dsmem);

    const int tid  = threadIdx.x;
    const int lane = tid & 31;
    const int w    = tid >> 5;
    const int g    = blockIdx.x >> 6;
    const int nt   = (blockIdx.x & 63) >> 3;
    const int kt   = blockIdx.x & 7;
    const int n0   = nt * 128;
    const int k0   = kt * 128;

    // ---- cache weight slice in smem (once) ----
    {
        const __nv_bfloat16* wh = WH + (size_t)g * H * H;
        const __nv_bfloat16* wl = WL + (size_t)g * H * H;
        #pragma unroll
        for (int it = 0; it < 16; it++) {
            int idx = tid + it * 256;          // 0..4095
            int mat = idx >> 11;               // 0 hi, 1 lo
            int rem = idx & 2047;
            int row = rem >> 4;                // 0..127
            int ch  = rem & 15;                // 16B chunks (256B/row)
            const __nv_bfloat16* src = (mat ? wl : wh) + (size_t)(n0 + row) * H + k0 + ch * 8;
            cpa16(sb + (mat ? W_LO : W_HI) + row * RP + ch * 16, src);
        }
        asm volatile("cp.async.commit_group;" ::: "memory");
        asm volatile("cp.async.wait_group 0;" ::: "memory");
        __syncthreads();
    }

    // phase-2 ownership: h-slice of 8, all 32 b
    const int p2_b  = tid >> 3;
    const int p2_h  = blockIdx.x * 8 + (tid & 7);
    const int p2_idx = p2_b * H + p2_h;

    unsigned tgt = 128;

    // ---- phase0: init latent state + split ----
    {
        float v = lat0[p2_idx];
        g_lat[p2_idx] = v;
        __nv_bfloat16 hi = __float2bfloat16(v);
        g_latH[p2_idx] = hi;
        g_latL[p2_idx] = __float2bfloat16(v - __bfloat162float(hi));
    }
    __threadfence();
    __syncthreads();
    if (tid == 0) {
        atomicAdd(bar, 1u);
        while (ldcg_u32(bar) < tgt) __nanosleep(64);
    }
    __syncthreads();
    tgt += 128;

    float* pbase = g_part2 + (size_t)((g * 8 + kt) * 32) * H;

    for (int t = 0; t < S; t++) {
        // ================= phase1: partial gate GEMM =================
        // stage latent hi/lo k-slice (L2 path; written by other CTAs)
        #pragma unroll
        for (int i = 0; i < 4; i++) {
            int idx = tid + i * 256;           // 0..1023
            int mat = idx >> 9;                // 0 hi, 1 lo
            int rem = idx & 511;
            int row = rem >> 4;                // b 0..31
            int ch  = rem & 15;
            const __nv_bfloat16* src = (mat ? g_latL : g_latH) + row * H + k0 + ch * 8;
            cpa16(sb + A_BASE + (mat ? A_LO : 0) + row * RP + ch * 16, src);
        }
        asm volatile("cp.async.commit_group;" ::: "memory");
        asm volatile("cp.async.wait_group 0;" ::: "memory");
        __syncthreads();

        float acc[2][2][4];
        #pragma unroll
        for (int i = 0; i < 2; i++)
            #pragma unroll
            for (int j = 0; j < 2; j++)
                #pragma unroll
                for (int q = 0; q < 4; q++) acc[i][j][q] = 0.f;

        uint32_t wbase = sb + (uint32_t)(w * 16) * RP;
        #pragma unroll
        for (int kk = 0; kk < 8; kk++) {
            uint32_t bhh[4], bll[4];
            {
                int brow = ((lane >> 4) << 3) + (lane & 7);
                int bk   = kk * 16 + ((lane >> 3) & 1) * 8;
                uint32_t ab = wbase + brow * RP + bk * 2;
                LDSM_X4(bhh[0], bhh[1], bhh[2], bhh[3], ab + W_HI);
                LDSM_X4(bll[0], bll[1], bll[2], bll[3], ab + W_LO);
            }
            uint32_t ahh[2][4], all[2][4];
            {
                int arow = lane & 15;
                int ak   = kk * 16 + (lane >> 4) * 8;
                #pragma unroll
                for (int mt = 0; mt < 2; mt++) {
                    uint32_t aa = sb + A_BASE + (mt * 16 + arow) * RP + ak * 2;
                    LDSM_X4(ahh[mt][0], ahh[mt][1], ahh[mt][2], ahh[mt][3], aa);
                    LDSM_X4(all[mt][0], all[mt][1], all[mt][2], all[mt][3], aa + A_LO);
                }
            }
            #pragma unroll
            for (int mt = 0; mt < 2; mt++)
                #pragma unroll
                for (int nn = 0; nn < 2; nn++)
                    MMA_BF16(acc[mt][nn], ahh[mt], bhh[nn*2], bhh[nn*2+1]);
            #pragma unroll
            for (int mt = 0; mt < 2; mt++)
                #pragma unroll
                for (int nn = 0; nn < 2; nn++)
                    MMA_BF16(acc[mt][nn], all[mt], bhh[nn*2], bhh[nn*2+1]);
            #pragma unroll
            for (int mt = 0; mt < 2; mt++)
                #pragma unroll
                for (int nn = 0; nn < 2; nn++)
                    MMA_BF16(acc[mt][nn], ahh[mt], bll[nn*2], bll[nn*2+1]);
        }
        __syncthreads();   // A smem reused next step

        // write partials [b][n0+col]
        #pragma unroll
        for (int mt = 0; mt < 2; mt++) {
            int r0 = mt * 16 + (lane >> 2);
            #pragma unroll
            for (int nn = 0; nn < 2; nn++) {
                int col = n0 + w * 16 + nn * 8 + (lane & 3) * 2;
                float2 v0 = { acc[mt][nn][0], acc[mt][nn][1] };
                float2 v1 = { acc[mt][nn][2], acc[mt][nn][3] };
                *reinterpret_cast<float2*>(pbase + (size_t)r0 * H + col)       = v0;
                *reinterpret_cast<float2*>(pbase + (size_t)(r0 + 8) * H + col) = v1;
            }
        }

        __threadfence();
        __syncthreads();
        if (tid == 0) {
            atomicAdd(bar, 1u);
            while (ldcg_u32(bar) < tgt) __nanosleep(64);
        }
        __syncthreads();
        tgt += 128;

        // ================= phase2: reduce + sigmoid + update =================
        {
            float si = 0.f, sf = 0.f;
            #pragma unroll
            for (int kc = 0; kc < 8; kc++) {
                si += __ldcg(g_part2 + (size_t)((0 * 8 + kc) * 32 + p2_b) * H + p2_h);
                sf += __ldcg(g_part2 + (size_t)((1 * 8 + kc) * 32 + p2_b) * H + p2_h);
            }
            size_t o = (size_t)t * BH + p2_idx;
            float ig = 1.f / (1.f + __expf(-(si + xi[o])));
            float fg = 1.f / (1.f + __expf(-(sf + xf[o])));
            float ln = ig * x[o] + fg * g_lat[p2_idx];
            g_lat[p2_idx] = ln;
            __nv_bfloat16 hi = __float2bfloat16(ln);
            g_latH[p2_idx] = hi;
            g_latL[p2_idx] = __float2bfloat16(ln - __bfloat162float(hi));
            lout[o] = ln;
            if (t == S - 1 && out_ig) { out_ig[p2_idx] = ig; out_fg[p2_idx] = fg; }
        }
        __threadfence();
        __syncthreads();
        if (tid == 0) {
            atomicAdd(bar, 1u);
            while (ldcg_u32(bar) < tgt) __nanosleep(64);
        }
        __syncthreads();
        tgt += 128;
    }
}

// -----------------------------------------------------------------------------
extern "C" void kernel_launch(void* const* d_in, const int* in_sizes, int n_in,
                              void* d_out, int out_size)
{
    (void)in_sizes; (void)n_in; (void)out_size;
    const int*   word   = (const int*)  d_in[0];
    const float* latent = (const float*)d_in[1];
    const float* emb    = (const float*)d_in[2];
    const float* h2o_w  = (const float*)d_in[3];
    const float* h2o_b  = (const float*)d_in[4];
    const float* Whi    = (const float*)d_in[5];
    const float* Wxi_w  = (const float*)d_in[6];
    const float* Wxi_b  = (const float*)d_in[7];
    const float* Whf    = (const float*)d_in[8];
    const float* Wxf_w  = (const float*)d_in[9];
    const float* Wxf_b  = (const float*)d_in[10];
    const float* Whi2   = (const float*)d_in[11];
    const float* Wxi2_w = (const float*)d_in[12];
    const float* Wxi2_b = (const float*)d_in[13];
    const float* Whf2   = (const float*)d_in[14];
    const float* Wxf2_w = (const float*)d_in[15];
    const float* Wxf2_b = (const float*)d_in[16];
    float* out = (float*)d_out;

    float *p_embeds, *p_xi, *p_xf, *p_l1, *p_lat;
    __nv_bfloat16 *p_Ah, *p_Al, *p_Bh, *p_Bl, *p_WgH, *p_WgL;
    unsigned* p_bar;
    cudaGetSymbolAddress((void**)&p_embeds, g_embeds);
    cudaGetSymbolAddress((void**)&p_xi,     g_xi);
    cudaGetSymbolAddress((void**)&p_xf,     g_xf);
    cudaGetSymbolAddress((void**)&p_l1,     g_l1);
    cudaGetSymbolAddress((void**)&p_lat,    g_lat);
    cudaGetSymbolAddress((void**)&p_Ah,     g_Ah);
    cudaGetSymbolAddress((void**)&p_Al,     g_Al);
    cudaGetSymbolAddress((void**)&p_Bh,     g_Bh);
    cudaGetSymbolAddress((void**)&p_Bl,     g_Bl);
    cudaGetSymbolAddress((void**)&p_WgH,    g_WgH);
    cudaGetSymbolAddress((void**)&p_WgL,    g_WgL);
    cudaGetSymbolAddress((void**)&p_bar,    g_bar);

    cudaFuncSetAttribute(k_hmma, cudaFuncAttributeMaxDynamicSharedMemorySize,
                         GEMM_SMEM);
    cudaFuncSetAttribute(k_rnn, cudaFuncAttributeMaxDynamicSharedMemorySize,
                         RNN_SMEM);

    const size_t OUT_LOG = BH;
    const size_t OUT_IG  = BH + (size_t)SB * V;
    const size_t OUT_FG  = OUT_IG + BH;

    cudaMemsetAsync(p_bar, 0, 2 * sizeof(unsigned));

    k_embed<<<SB, 256>>>(word, emb);

    const int ACT4 = SB * H / 4;
    const int W4   = H * H / 4;
    const int HO4  = V * H / 4;

    // split recurrent weights (bf16 hi/lo), layout [n][k] as-is
    k_split<<<W4/256, 256>>>(Whi,  p_WgH + 0*H*H, p_WgL + 0*H*H, W4);
    k_split<<<W4/256, 256>>>(Whf,  p_WgH + 1*H*H, p_WgL + 1*H*H, W4);
    k_split<<<W4/256, 256>>>(Whi2, p_WgH + 2*H*H, p_WgL + 2*H*H, W4);
    k_split<<<W4/256, 256>>>(Whf2, p_WgH + 3*H*H, p_WgL + 3*H*H, W4);

    // layer-1 input gate preactivations via tensor cores
    k_split<<<ACT4/256, 256>>>(p_embeds, p_Ah, p_Al, ACT4);
    dim3 ggrid(SB/128, H/128);
    k_split<<<W4/256, 256>>>(Wxi_w, p_Bh, p_Bl, W4);
    k_hmma<<<ggrid, 256, GEMM_SMEM>>>(p_Ah, p_Al, p_Bh, p_Bl, Wxi_b, p_xi, H, H);
    k_split<<<W4/256, 256>>>(Wxf_w, p_Bh, p_Bl, W4);
    k_hmma<<<ggrid, 256, GEMM_SMEM>>>(p_Ah, p_Al, p_Bh, p_Bl, Wxf_b, p_xf, H, H);

    // layer-1 recurrence (persistent)
    k_rnn<<<128, 256, RNN_SMEM>>>(latent, p_xi, p_xf, p_embeds, p_l1,
                                  p_WgH, p_WgL, p_bar, nullptr, nullptr);

    // layer-2 input gate preactivations
    k_split<<<ACT4/256, 256>>>(p_l1, p_Ah, p_Al, ACT4);
    k_split<<<W4/256, 256>>>(Wxi2_w, p_Bh, p_Bl, W4);
    k_hmma<<<ggrid, 256, GEMM_SMEM>>>(p_Ah, p_Al, p_Bh, p_Bl, Wxi2_b, p_xi, H, H);
    k_split<<<W4/256, 256>>>(Wxf2_w, p_Bh, p_Bl, W4);
    k_hmma<<<ggrid, 256, GEMM_SMEM>>>(p_Ah, p_Al, p_Bh, p_Bl, Wxf2_b, p_xf, H, H);

    // layer-2 recurrence (persistent); initial latent = g_lat (layer-1 final)
    k_rnn<<<128, 256, RNN_SMEM>>>(p_lat, p_xi, p_xf, p_l1, p_embeds,
                                  p_WgH + 2*H*H, p_WgL + 2*H*H, p_bar + 1,
                                  out + OUT_IG, out + OUT_FG);

    // logits via tensor cores
    k_split<<<ACT4/256, 256>>>(p_embeds /* = l2_out */, p_Ah, p_Al, ACT4);
    k_split<<<HO4/256, 256>>>(h2o_w, p_Bh, p_Bl, HO4);
    dim3 lgrid(SB/128, V/128);
    k_hmma<<<lgrid, 256, GEMM_SMEM>>>(p_Ah, p_Al, p_Bh, p_Bl, h2o_b,
                                      out + OUT_LOG, H, V);

    // final latent
    cudaMemcpyAsync(out, p_lat, (size_t)BH * sizeof(float),
                    cudaMemcpyDeviceToDevice);
}

// round 8
// speedup vs baseline: 1.9603x; 1.0012x over previous
#include <cuda_runtime.h>
#include <cuda_bf16.h>
#include <math.h>
#include <stdint.h>

#define S 128
#define B 32
#define H 1024
#define E 1024
#define V 32000
#define SB (S*B)        /* 4096  */
#define BH (B*H)        /* 32768 */

// ---------------- scratch (device globals; no allocations allowed) ----------
__device__ float g_embeds[SB*H];   // embeds for layer1, reused as l2_out
__device__ float g_xi[SB*H];
__device__ float g_xf[SB*H];
__device__ float g_l1[SB*H];
__device__ float g_lat[BH];                    // fp32 latent state
__device__ __nv_bfloat16 g_latH[BH];
__device__ __nv_bfloat16 g_latL[BH];
__device__ float g_part2[2*8*B*H];             // [gate][kt][b][h]
__device__ unsigned g_bar[2];                  // per-layer barrier counters
// recurrent weights, bf16 split: [mat 0..3][n=h_out][k=h_in]
__device__ __nv_bfloat16 g_WgH[4*H*H];
__device__ __nv_bfloat16 g_WgL[4*H*H];
// bf16 split operands for tensor-core GEMMs
__device__ __nv_bfloat16 g_Ah[SB*H];
__device__ __nv_bfloat16 g_Al[SB*H];
__device__ __nv_bfloat16 g_Bh[(size_t)V*H];
__device__ __nv_bfloat16 g_Bl[(size_t)V*H];

// ============================ helpers ========================================
__device__ __forceinline__ uint32_t smem_u32(const void* p) {
    uint32_t a;
    asm("{ .reg .u64 t; cvta.to.shared.u64 t, %1; cvt.u32.u64 %0, t; }"
        : "=r"(a) : "l"(p));
    return a;
}
__device__ __forceinline__ void cpa16(uint32_t s, const void* g) {
    asm volatile("cp.async.cg.shared.global [%0], [%1], 16;" :: "r"(s), "l"(g) : "memory");
}
__device__ __forceinline__ unsigned ldcg_u32(const unsigned* p) {
    unsigned v;
    asm volatile("ld.global.cg.u32 %0, [%1];" : "=r"(v) : "l"(p));
    return v;
}
#define LDSM_X4(r0,r1,r2,r3,addr) \
    asm volatile("ldmatrix.sync.aligned.m8n8.x4.shared.b16 {%0,%1,%2,%3}, [%4];" \
        : "=r"(r0),"=r"(r1),"=r"(r2),"=r"(r3) : "r"(addr))
#define MMA_BF16(c, a, b0, b1) \
    asm volatile("mma.sync.aligned.m16n8k16.row.col.f32.bf16.bf16.f32 " \
        "{%0,%1,%2,%3}, {%4,%5,%6,%7}, {%8,%9}, {%0,%1,%2,%3};" \
        : "+f"((c)[0]),"+f"((c)[1]),"+f"((c)[2]),"+f"((c)[3]) \
        : "r"((a)[0]),"r"((a)[1]),"r"((a)[2]),"r"((a)[3]), "r"(b0),"r"(b1))

// ================= split-bf16 HMMA GEMM (unchanged R5 winner) ================
#define ROWP 40
#define MAT_B (128*ROWP*2)
#define STG_B (4*MAT_B)
#define GEMM_SMEM (2*STG_B)

__global__ void __launch_bounds__(256, 2)
k_hmma(const __nv_bfloat16* __restrict__ Ah, const __nv_bfloat16* __restrict__ Al,
       const __nv_bfloat16* __restrict__ Bh, const __nv_bfloat16* __restrict__ Bl,
       const float* __restrict__ bias, float* __restrict__ C,
       int Kdim, int Nld)
{
    extern __shared__ __align__(16) char dsmem[];
    uint32_t sbase = smem_u32(dsmem);

    const int tid  = threadIdx.x;
    const int lane = tid & 31;
    const int warp = tid >> 5;
    const int wm   = warp & 1;
    const int wn   = warp >> 1;
    const int m0   = blockIdx.x * 128;
    const int n0   = blockIdx.y * 128;

    float c[4][4][4];
    #pragma unroll
    for (int i = 0; i < 4; i++)
        #pragma unroll
        for (int j = 0; j < 4; j++)
            #pragma unroll
            for (int q = 0; q < 4; q++) c[i][j][q] = 0.f;

    const int NS = Kdim >> 5;

    auto load_stage = [&](int s, int buf) {
        int k0 = s * 32;
        uint32_t sb = sbase + buf * STG_B;
        #pragma unroll
        for (int it = 0; it < 8; it++) {
            int idx = tid + it * 256;
            int mat = idx >> 9;
            int rem = idx & 511;
            int row = rem >> 2;
            int ch  = rem & 3;
            const __nv_bfloat16* g;
            if (mat == 0)      g = Ah + (size_t)(m0 + row) * Kdim;
            else if (mat == 1) g = Al + (size_t)(m0 + row) * Kdim;
            else if (mat == 2) g = Bh + (size_t)(n0 + row) * Kdim;
            else               g = Bl + (size_t)(n0 + row) * Kdim;
            cpa16(sb + mat * MAT_B + row * 80 + ch * 16, g + k0 + ch * 8);
        }
        asm volatile("cp.async.commit_group;" ::: "memory");
    };

    load_stage(0, 0);

    for (int s = 0; s < NS; s++) {
        int buf = s & 1;
        if (s + 1 < NS) {
            load_stage(s + 1, (s + 1) & 1);
            asm volatile("cp.async.wait_group 1;" ::: "memory");
        } else {
            asm volatile("cp.async.wait_group 0;" ::: "memory");
        }
        __syncthreads();

        uint32_t sb = sbase + buf * STG_B;
        #pragma unroll
        for (int ks = 0; ks < 2; ks++) {
            uint32_t bh[2][4], bl[2][4];
            {
                int brow = wn * 32 + ((lane >> 4) << 3) + (lane & 7);
                int bk   = ks * 16 + ((lane >> 3) & 1) * 8;
                #pragma unroll
                for (int p = 0; p < 2; p++) {
                    uint32_t ab = sb + 2 * MAT_B + (brow + p * 16) * 80 + bk * 2;
                    LDSM_X4(bh[p][0], bh[p][1], bh[p][2], bh[p][3], ab);
                    LDSM_X4(bl[p][0], bl[p][1], bl[p][2], bl[p][3], ab + MAT_B);
                }
            }
            int arow = wm * 64 + (lane & 15);
            int ak   = ks * 16 + (lane >> 4) * 8;
            #pragma unroll
            for (int mt = 0; mt < 4; mt++) {
                uint32_t aa = sb + (arow + mt * 16) * 80 + ak * 2;
                uint32_t ah[4], al[4];
                LDSM_X4(ah[0], ah[1], ah[2], ah[3], aa);
                LDSM_X4(al[0], al[1], al[2], al[3], aa + MAT_B);
                #pragma unroll
                for (int p = 0; p < 2; p++) {
                    #pragma unroll
                    for (int hf = 0; hf < 2; hf++) {
                        int nt = p * 2 + hf;
                        uint32_t b0h = bh[p][hf*2], b1h = bh[p][hf*2+1];
                        uint32_t b0l = bl[p][hf*2], b1l = bl[p][hf*2+1];
                        MMA_BF16(c[mt][nt], ah, b0h, b1h);
                        MMA_BF16(c[mt][nt], al, b0h, b1h);
                        MMA_BF16(c[mt][nt], ah, b0l, b1l);
                    }
                }
            }
        }
        __syncthreads();
    }

    const int mw = m0 + wm * 64;
    const int nw = n0 + wn * 32;
    #pragma unroll
    for (int mt = 0; mt < 4; mt++) {
        int r = mw + mt * 16 + (lane >> 2);
        #pragma unroll
        for (int nt = 0; nt < 4; nt++) {
            int cc = nw + nt * 8 + (lane & 3) * 2;
            float bx = bias[cc], by = bias[cc + 1];
            float2 v0 = { c[mt][nt][0] + bx, c[mt][nt][1] + by };
            float2 v1 = { c[mt][nt][2] + bx, c[mt][nt][3] + by };
            *reinterpret_cast<float2*>(C + (size_t)r * Nld + cc)       = v0;
            *reinterpret_cast<float2*>(C + (size_t)(r + 8) * Nld + cc) = v1;
        }
    }
}

// ---------------- fp32 -> bf16 hi/lo split (MLP-4) ----------------------------
__global__ void k_split(const float* __restrict__ x,
                        __nv_bfloat16* __restrict__ hi,
                        __nv_bfloat16* __restrict__ lo, int n4)
{
    int base = blockIdx.x * 1024 + threadIdx.x;
    float4 v[4];
    int   ok[4];
    #pragma unroll
    for (int j = 0; j < 4; j++) {
        int i = base + j * 256;
        ok[j] = (i < n4);
        if (ok[j]) v[j] = reinterpret_cast<const float4*>(x)[i];
    }
    #pragma unroll
    for (int j = 0; j < 4; j++) {
        if (!ok[j]) continue;
        int i = base + j * 256;
        __nv_bfloat16 h0 = __float2bfloat16(v[j].x);
        __nv_bfloat16 h1 = __float2bfloat16(v[j].y);
        __nv_bfloat16 h2 = __float2bfloat16(v[j].z);
        __nv_bfloat16 h3 = __float2bfloat16(v[j].w);
        __nv_bfloat16 l0 = __float2bfloat16(v[j].x - __bfloat162float(h0));
        __nv_bfloat16 l1 = __float2bfloat16(v[j].y - __bfloat162float(h1));
        __nv_bfloat16 l2 = __float2bfloat16(v[j].z - __bfloat162float(h2));
        __nv_bfloat16 l3 = __float2bfloat16(v[j].w - __bfloat162float(h3));
        __nv_bfloat162 hp0 = {h0, h1}, hp1 = {h2, h3};
        __nv_bfloat162 lp0 = {l0, l1}, lp1 = {l2, l3};
        reinterpret_cast<__nv_bfloat162*>(hi)[i * 2 + 0] = hp0;
        reinterpret_cast<__nv_bfloat162*>(hi)[i * 2 + 1] = hp1;
        reinterpret_cast<__nv_bfloat162*>(lo)[i * 2 + 0] = lp0;
        reinterpret_cast<__nv_bfloat162*>(lo)[i * 2 + 1] = lp1;
    }
}

// ---------------- embedding gather + inline split -----------------------------
__global__ void k_embed(const int* __restrict__ word, const float* __restrict__ emb,
                        __nv_bfloat16* __restrict__ aH, __nv_bfloat16* __restrict__ aL)
{
    int row = blockIdx.x;
    int w = word[row];
    float4 v = reinterpret_cast<const float4*>(emb + (size_t)w * E)[threadIdx.x];
    size_t o4 = (size_t)row * 256 + threadIdx.x;
    reinterpret_cast<float4*>(g_embeds)[o4] = v;
    __nv_bfloat16 h0 = __float2bfloat16(v.x);
    __nv_bfloat16 h1 = __float2bfloat16(v.y);
    __nv_bfloat16 h2 = __float2bfloat16(v.z);
    __nv_bfloat16 h3 = __float2bfloat16(v.w);
    __nv_bfloat16 l0 = __float2bfloat16(v.x - __bfloat162float(h0));
    __nv_bfloat16 l1 = __float2bfloat16(v.y - __bfloat162float(h1));
    __nv_bfloat16 l2 = __float2bfloat16(v.z - __bfloat162float(h2));
    __nv_bfloat16 l3 = __float2bfloat16(v.w - __bfloat162float(h3));
    __nv_bfloat162 hp0 = {h0, h1}, hp1 = {h2, h3};
    __nv_bfloat162 lp0 = {l0, l1}, lp1 = {l2, l3};
    reinterpret_cast<__nv_bfloat162*>(aH)[o4 * 2 + 0] = hp0;
    reinterpret_cast<__nv_bfloat162*>(aH)[o4 * 2 + 1] = hp1;
    reinterpret_cast<__nv_bfloat162*>(aL)[o4 * 2 + 0] = lp0;
    reinterpret_cast<__nv_bfloat162*>(aL)[o4 * 2 + 1] = lp1;
}

// ================= persistent recurrence (one launch per layer) ==============
#define RP 272
#define W_HI 0
#define W_LO (128*RP)
#define A_BASE (2*128*RP)
#define A_LO (32*RP)
#define RNN_SMEM (A_BASE + 2*32*RP)

__global__ void __launch_bounds__(256)
k_rnn(const float* __restrict__ lat0,
      const float* __restrict__ xi, const float* __restrict__ xf,
      const float* __restrict__ x, float* __restrict__ lout,
      __nv_bfloat16* __restrict__ loutH, __nv_bfloat16* __restrict__ loutL,
      const __nv_bfloat16* __restrict__ WH, const __nv_bfloat16* __restrict__ WL,
      unsigned* __restrict__ bar,
      float* __restrict__ out_ig, float* __restrict__ out_fg)
{
    extern __shared__ __align__(16) char dsmem[];
    uint32_t sb = smem_u32(dsmem);

    const int tid  = threadIdx.x;
    const int lane = tid & 31;
    const int w    = tid >> 5;
    const int g    = blockIdx.x >> 6;
    const int nt   = (blockIdx.x & 63) >> 3;
    const int kt   = blockIdx.x & 7;
    const int n0   = nt * 128;
    const int k0   = kt * 128;

    // ---- cache weight slice in smem (once) ----
    {
        const __nv_bfloat16* wh = WH + (size_t)g * H * H;
        const __nv_bfloat16* wl = WL + (size_t)g * H * H;
        #pragma unroll
        for (int it = 0; it < 16; it++) {
            int idx = tid + it * 256;
            int mat = idx >> 11;
            int rem = idx & 2047;
            int row = rem >> 4;
            int ch  = rem & 15;
            const __nv_bfloat16* src = (mat ? wl : wh) + (size_t)(n0 + row) * H + k0 + ch * 8;
            cpa16(sb + (mat ? W_LO : W_HI) + row * RP + ch * 16, src);
        }
        asm volatile("cp.async.commit_group;" ::: "memory");
        asm volatile("cp.async.wait_group 0;" ::: "memory");
        __syncthreads();
    }

    const int p2_b  = tid >> 3;
    const int p2_h  = blockIdx.x * 8 + (tid & 7);
    const int p2_idx = p2_b * H + p2_h;

    unsigned tgt = 128;

    // ---- phase0: init latent state + split ----
    {
        float v = lat0[p2_idx];
        g_lat[p2_idx] = v;
        __nv_bfloat16 hi = __float2bfloat16(v);
        g_latH[p2_idx] = hi;
        g_latL[p2_idx] = __float2bfloat16(v - __bfloat162float(hi));
    }
    __threadfence();
    __syncthreads();
    if (tid == 0) {
        atomicAdd(bar, 1u);
        while (ldcg_u32(bar) < tgt) __nanosleep(64);
    }
    __syncthreads();
    tgt += 128;

    float* pbase = g_part2 + (size_t)((g * 8 + kt) * 32) * H;

    for (int t = 0; t < S; t++) {
        // ================= phase1: partial gate GEMM =================
        #pragma unroll
        for (int i = 0; i < 4; i++) {
            int idx = tid + i * 256;
            int mat = idx >> 9;
            int rem = idx & 511;
            int row = rem >> 4;
            int ch  = rem & 15;
            const __nv_bfloat16* src = (mat ? g_latL : g_latH) + row * H + k0 + ch * 8;
            cpa16(sb + A_BASE + (mat ? A_LO : 0) + row * RP + ch * 16, src);
        }
        asm volatile("cp.async.commit_group;" ::: "memory");
        asm volatile("cp.async.wait_group 0;" ::: "memory");
        __syncthreads();

        float acc[2][2][4];
        #pragma unroll
        for (int i = 0; i < 2; i++)
            #pragma unroll
            for (int j = 0; j < 2; j++)
                #pragma unroll
                for (int q = 0; q < 4; q++) acc[i][j][q] = 0.f;

        uint32_t wbase = sb + (uint32_t)(w * 16) * RP;
        #pragma unroll
        for (int kk = 0; kk < 8; kk++) {
            uint32_t bhh[4], bll[4];
            {
                int brow = ((lane >> 4) << 3) + (lane & 7);
                int bk   = kk * 16 + ((lane >> 3) & 1) * 8;
                uint32_t ab = wbase + brow * RP + bk * 2;
                LDSM_X4(bhh[0], bhh[1], bhh[2], bhh[3], ab + W_HI);
                LDSM_X4(bll[0], bll[1], bll[2], bll[3], ab + W_LO);
            }
            uint32_t ahh[2][4], all[2][4];
            {
                int arow = lane & 15;
                int ak   = kk * 16 + (lane >> 4) * 8;
                #pragma unroll
                for (int mt = 0; mt < 2; mt++) {
                    uint32_t aa = sb + A_BASE + (mt * 16 + arow) * RP + ak * 2;
                    LDSM_X4(ahh[mt][0], ahh[mt][1], ahh[mt][2], ahh[mt][3], aa);
                    LDSM_X4(all[mt][0], all[mt][1], all[mt][2], all[mt][3], aa + A_LO);
                }
            }
            #pragma unroll
            for (int mt = 0; mt < 2; mt++)
                #pragma unroll
                for (int nn = 0; nn < 2; nn++)
                    MMA_BF16(acc[mt][nn], ahh[mt], bhh[nn*2], bhh[nn*2+1]);
            #pragma unroll
            for (int mt = 0; mt < 2; mt++)
                #pragma unroll
                for (int nn = 0; nn < 2; nn++)
                    MMA_BF16(acc[mt][nn], all[mt], bhh[nn*2], bhh[nn*2+1]);
            #pragma unroll
            for (int mt = 0; mt < 2; mt++)
                #pragma unroll
                for (int nn = 0; nn < 2; nn++)
                    MMA_BF16(acc[mt][nn], ahh[mt], bll[nn*2], bll[nn*2+1]);
        }
        __syncthreads();

        #pragma unroll
        for (int mt = 0; mt < 2; mt++) {
            int r0 = mt * 16 + (lane >> 2);
            #pragma unroll
            for (int nn = 0; nn < 2; nn++) {
                int col = n0 + w * 16 + nn * 8 + (lane & 3) * 2;
                float2 v0 = { acc[mt][nn][0], acc[mt][nn][1] };
                float2 v1 = { acc[mt][nn][2], acc[mt][nn][3] };
                *reinterpret_cast<float2*>(pbase + (size_t)r0 * H + col)       = v0;
                *reinterpret_cast<float2*>(pbase + (size_t)(r0 + 8) * H + col) = v1;
            }
        }

        __threadfence();
        __syncthreads();
        if (tid == 0) {
            atomicAdd(bar, 1u);
            while (ldcg_u32(bar) < tgt) __nanosleep(64);
        }
        __syncthreads();
        tgt += 128;

        // ================= phase2: reduce + sigmoid + update =================
        {
            float si = 0.f, sf = 0.f;
            #pragma unroll
            for (int kc = 0; kc < 8; kc++) {
                si += __ldcg(g_part2 + (size_t)((0 * 8 + kc) * 32 + p2_b) * H + p2_h);
                sf += __ldcg(g_part2 + (size_t)((1 * 8 + kc) * 32 + p2_b) * H + p2_h);
            }
            size_t o = (size_t)t * BH + p2_idx;
            float ig = 1.f / (1.f + __expf(-(si + xi[o])));
            float fg = 1.f / (1.f + __expf(-(sf + xf[o])));
            float ln = ig * x[o] + fg * g_lat[p2_idx];
            g_lat[p2_idx] = ln;
            __nv_bfloat16 hi = __float2bfloat16(ln);
            __nv_bfloat16 lo = __float2bfloat16(ln - __bfloat162float(hi));
            g_latH[p2_idx] = hi;
            g_latL[p2_idx] = lo;
            lout[o]  = ln;
            loutH[o] = hi;
            loutL[o] = lo;
            if (t == S - 1 && out_ig) { out_ig[p2_idx] = ig; out_fg[p2_idx] = fg; }
        }
        __threadfence();
        __syncthreads();
        if (tid == 0) {
            atomicAdd(bar, 1u);
            while (ldcg_u32(bar) < tgt) __nanosleep(64);
        }
        __syncthreads();
        tgt += 128;
    }
}

// -----------------------------------------------------------------------------
extern "C" void kernel_launch(void* const* d_in, const int* in_sizes, int n_in,
                              void* d_out, int out_size)
{
    (void)in_sizes; (void)n_in; (void)out_size;
    const int*   word   = (const int*)  d_in[0];
    const float* latent = (const float*)d_in[1];
    const float* emb    = (const float*)d_in[2];
    const float* h2o_w  = (const float*)d_in[3];
    const float* h2o_b  = (const float*)d_in[4];
    const float* Whi    = (const float*)d_in[5];
    const float* Wxi_w  = (const float*)d_in[6];
    const float* Wxi_b  = (const float*)d_in[7];
    const float* Whf    = (const float*)d_in[8];
    const float* Wxf_w  = (const float*)d_in[9];
    const float* Wxf_b  = (const float*)d_in[10];
    const float* Whi2   = (const float*)d_in[11];
    const float* Wxi2_w = (const float*)d_in[12];
    const float* Wxi2_b = (const float*)d_in[13];
    const float* Whf2   = (const float*)d_in[14];
    const float* Wxf2_w = (const float*)d_in[15];
    const float* Wxf2_b = (const float*)d_in[16];
    float* out = (float*)d_out;

    float *p_embeds, *p_xi, *p_xf, *p_l1, *p_lat;
    __nv_bfloat16 *p_Ah, *p_Al, *p_Bh, *p_Bl, *p_WgH, *p_WgL;
    unsigned* p_bar;
    cudaGetSymbolAddress((void**)&p_embeds, g_embeds);
    cudaGetSymbolAddress((void**)&p_xi,     g_xi);
    cudaGetSymbolAddress((void**)&p_xf,     g_xf);
    cudaGetSymbolAddress((void**)&p_l1,     g_l1);
    cudaGetSymbolAddress((void**)&p_lat,    g_lat);
    cudaGetSymbolAddress((void**)&p_Ah,     g_Ah);
    cudaGetSymbolAddress((void**)&p_Al,     g_Al);
    cudaGetSymbolAddress((void**)&p_Bh,     g_Bh);
    cudaGetSymbolAddress((void**)&p_Bl,     g_Bl);
    cudaGetSymbolAddress((void**)&p_WgH,    g_WgH);
    cudaGetSymbolAddress((void**)&p_WgL,    g_WgL);
    cudaGetSymbolAddress((void**)&p_bar,    g_bar);

    cudaFuncSetAttribute(k_hmma, cudaFuncAttributeMaxDynamicSharedMemorySize,
                         GEMM_SMEM);
    cudaFuncSetAttribute(k_rnn, cudaFuncAttributeMaxDynamicSharedMemorySize,
                         RNN_SMEM);

    const size_t OUT_LOG = BH;
    const size_t OUT_IG  = BH + (size_t)SB * V;
    const size_t OUT_FG  = OUT_IG + BH;

    cudaMemsetAsync(p_bar, 0, 2 * sizeof(unsigned));

    // embed gather + inline split -> (g_embeds fp32, g_Ah/g_Al bf16)
    k_embed<<<SB, 256>>>(word, emb, p_Ah, p_Al);

    const int W4  = H * H / 4;       // 262144
    const int HO4 = V * H / 4;       // 8192000
    const int WB  = (W4  + 1023) / 1024;
    const int HOB = (HO4 + 1023) / 1024;

    // split recurrent weights (bf16 hi/lo), layout [n][k] as-is
    k_split<<<WB, 256>>>(Whi,  p_WgH + 0*H*H, p_WgL + 0*H*H, W4);
    k_split<<<WB, 256>>>(Whf,  p_WgH + 1*H*H, p_WgL + 1*H*H, W4);
    k_split<<<WB, 256>>>(Whi2, p_WgH + 2*H*H, p_WgL + 2*H*H, W4);
    k_split<<<WB, 256>>>(Whf2, p_WgH + 3*H*H, p_WgL + 3*H*H, W4);

    // layer-1 input gate preactivations via tensor cores
    dim3 ggrid(SB/128, H/128);
    k_split<<<WB, 256>>>(Wxi_w, p_Bh, p_Bl, W4);
    k_hmma<<<ggrid, 256, GEMM_SMEM>>>(p_Ah, p_Al, p_Bh, p_Bl, Wxi_b, p_xi, H, H);
    k_split<<<WB, 256>>>(Wxf_w, p_Bh, p_Bl, W4);
    k_hmma<<<ggrid, 256, GEMM_SMEM>>>(p_Ah, p_Al, p_Bh, p_Bl, Wxf_b, p_xf, H, H);

    // layer-1 recurrence (persistent); writes l1 fp32 + split into g_Ah/g_Al
    k_rnn<<<128, 256, RNN_SMEM>>>(latent, p_xi, p_xf, p_embeds, p_l1,
                                  p_Ah, p_Al,
                                  p_WgH, p_WgL, p_bar, nullptr, nullptr);

    // layer-2 input gate preactivations (A = l1 split, already in g_Ah/g_Al)
    k_split<<<WB, 256>>>(Wxi2_w, p_Bh, p_Bl, W4);
    k_hmma<<<ggrid, 256, GEMM_SMEM>>>(p_Ah, p_Al, p_Bh, p_Bl, Wxi2_b, p_xi, H, H);
    k_split<<<WB, 256>>>(Wxf2_w, p_Bh, p_Bl, W4);
    k_hmma<<<ggrid, 256, GEMM_SMEM>>>(p_Ah, p_Al, p_Bh, p_Bl, Wxf2_b, p_xf, H, H);

    // layer-2 recurrence; writes l2_out fp32 (g_embeds) + split into g_Ah/g_Al
    k_rnn<<<128, 256, RNN_SMEM>>>(p_lat, p_xi, p_xf, p_l1, p_embeds,
                                  p_Ah, p_Al,
                                  p_WgH + 2*H*H, p_WgL + 2*H*H, p_bar + 1,
                                  out + OUT_IG, out + OUT_FG);

    // logits via tensor cores (A = l2_out split, already in g_Ah/g_Al)
    k_split<<<HOB, 256>>>(h2o_w, p_Bh, p_Bl, HO4);
    dim3 lgrid(SB/128, V/128);
    k_hmma<<<lgrid, 256, GEMM_SMEM>>>(p_Ah, p_Al, p_Bh, p_Bl, h2o_b,
                                      out + OUT_LOG, H, V);

    // final latent
    cudaMemcpyAsync(out, p_lat, (size_t)BH * sizeof(float),
                    cudaMemcpyDeviceToDevice);
}